// round 2
// baseline (speedup 1.0000x reference)
#include <cuda_runtime.h>
#include <math.h>
#include <stdint.h>

#define BB   64
#define TT   128
#define DD   850
#define D2   1700
#define CIN  910
#define NCC  42
#define NNER 30
#define NPOS 30

// Scratch (static device globals; no runtime allocation)
__device__ float g_combined[TT * BB * CIN];
__device__ float g_x[TT * BB * DD];
__device__ float g_xw0[TT * BB * D2];
__device__ float g_hiddens[TT * BB * DD];
__device__ float g_states[9][BB * DD];

struct StepInfo { int wmat; int pred; int act; };
// act: 0 tanh, 1 relu, 2 sigmoid, 3 identity
__constant__ StepInfo c_steps[9] = {
    {0, -1, 0},  // s0 cell (tanh)
    {1,  0, 2},  // s1 sigmoid
    {2,  1, 1},  // s2 relu
    {3,  1, 1},  // s3 relu
    {4,  1, 3},  // s4 identity
    {5,  2, 0},  // s5 tanh
    {6,  5, 2},  // s6 sigmoid
    {7,  3, 0},  // s7 tanh
    {8,  5, 1},  // s8 relu
};

__device__ __forceinline__ float sigmoidf_(float x) { return 1.f / (1.f + expf(-x)); }
__device__ __forceinline__ float actf_(float x, int code) {
    switch (code) {
        case 0:  return tanhf(x);
        case 1:  return fmaxf(x, 0.f);
        case 2:  return sigmoidf_(x);
        default: return x;
    }
}

// ---------------------------------------------------------------------------
// K1: gather embeddings into g_combined rows (r = t*BB + b)
// ---------------------------------------------------------------------------
__global__ void gather_kernel(const int* __restrict__ tokens,
                              const int* __restrict__ ner,
                              const int* __restrict__ pos,
                              const float* __restrict__ encW,
                              const float* __restrict__ nerW,
                              const float* __restrict__ posW) {
    int r = blockIdx.x;
    int b = r & (BB - 1);
    int t = r >> 6;
    int tok = tokens[b * TT + t];
    int nid = ner[b * TT + t];
    int pid = pos[b * TT + t];
    float* dst = g_combined + (size_t)r * CIN;
    for (int c = threadIdx.x; c < CIN; c += blockDim.x) {
        float v;
        if (c < DD)             v = encW[(size_t)tok * DD + c];
        else if (c < DD + NNER) v = nerW[nid * NNER + (c - DD)];
        else                    v = posW[pid * NPOS + (c - DD - NNER)];
        dst[c] = v;
    }
}

// ---------------------------------------------------------------------------
// K2: generic tiled fp32 GEMM, C = A * op(B) (+ bias). BM=BN=64, BK=16.
// TRANSB: B is [N,K] row-major; else [K,N] row-major.
// ---------------------------------------------------------------------------
template <bool TRANSB, bool ADDBIAS>
__global__ void gemm_tile(const float* __restrict__ A, const float* __restrict__ Bm,
                          const float* __restrict__ bias, float* __restrict__ C,
                          int M, int N, int K, int lda, int ldb, int ldc) {
    __shared__ __align__(16) float As[16 * 64];
    __shared__ __align__(16) float Bs[16 * 64];
    int tid = threadIdx.x;
    int m0 = blockIdx.y * 64;
    int n0 = blockIdx.x * 64;
    int mi = tid & 15;
    int ni = tid >> 4;
    float acc[4][4] = {};

    for (int k0 = 0; k0 < K; k0 += 16) {
        __syncthreads();
        #pragma unroll
        for (int i = 0; i < 4; i++) {          // A: 64m x 16k -> As[k][m]
            int e = tid + 256 * i;
            int m = e >> 4, k = e & 15;
            int kk = k0 + k;
            float v = 0.f;
            if (kk < K) v = A[(size_t)(m0 + m) * lda + kk];
            As[k * 64 + m] = v;
        }
        #pragma unroll
        for (int i = 0; i < 4; i++) {          // B -> Bs[k][n]
            int e = tid + 256 * i;
            float v = 0.f;
            if (TRANSB) {
                int n = e >> 4, k = e & 15;
                int kk = k0 + k, nn = n0 + n;
                if (kk < K && nn < N) v = Bm[(size_t)nn * ldb + kk];
                Bs[k * 64 + n] = v;
            } else {
                int k = e >> 6, n = e & 63;
                int kk = k0 + k, nn = n0 + n;
                if (kk < K && nn < N) v = Bm[(size_t)kk * ldb + nn];
                Bs[k * 64 + n] = v;
            }
        }
        __syncthreads();
        #pragma unroll
        for (int k = 0; k < 16; k++) {
            float4 a4 = *(const float4*)(As + k * 64 + mi * 4);
            float4 b4 = *(const float4*)(Bs + k * 64 + ni * 4);
            acc[0][0] = fmaf(a4.x, b4.x, acc[0][0]);
            acc[0][1] = fmaf(a4.x, b4.y, acc[0][1]);
            acc[0][2] = fmaf(a4.x, b4.z, acc[0][2]);
            acc[0][3] = fmaf(a4.x, b4.w, acc[0][3]);
            acc[1][0] = fmaf(a4.y, b4.x, acc[1][0]);
            acc[1][1] = fmaf(a4.y, b4.y, acc[1][1]);
            acc[1][2] = fmaf(a4.y, b4.z, acc[1][2]);
            acc[1][3] = fmaf(a4.y, b4.w, acc[1][3]);
            acc[2][0] = fmaf(a4.z, b4.x, acc[2][0]);
            acc[2][1] = fmaf(a4.z, b4.y, acc[2][1]);
            acc[2][2] = fmaf(a4.z, b4.z, acc[2][2]);
            acc[2][3] = fmaf(a4.z, b4.w, acc[2][3]);
            acc[3][0] = fmaf(a4.w, b4.x, acc[3][0]);
            acc[3][1] = fmaf(a4.w, b4.y, acc[3][1]);
            acc[3][2] = fmaf(a4.w, b4.z, acc[3][2]);
            acc[3][3] = fmaf(a4.w, b4.w, acc[3][3]);
        }
    }
    #pragma unroll
    for (int r = 0; r < 4; r++) {
        int mm = m0 + mi * 4 + r;
        #pragma unroll
        for (int c = 0; c < 4; c++) {
            int nn = n0 + ni * 4 + c;
            if (nn < N) {
                float v = acc[r][c];
                if (ADDBIAS) v += bias[nn];
                C[(size_t)mm * ldc + nn] = v;
            }
        }
    }
}

// ---------------------------------------------------------------------------
// K3: one dependency level of one timestep. grid = (54 pair-blocks, nsteps).
// Each CTA computes columns [p0,p0+16) of both halves (c at p, h at 850+p) of
// s_pred @ W, then the gated update. Cell adds precomputed x@W0_top; block 0
// of the cell also writes hiddens[t-1] = mean(s1..s8) while staging A.
// ---------------------------------------------------------------------------
__global__ void recur_level(int t, int sid0, int sid1, int sid2,
                            const float* __restrict__ W0,
                            const float* __restrict__ Ws,
                            const float* __restrict__ hidden_in) {
    int sid = (blockIdx.y == 0) ? sid0 : (blockIdx.y == 1 ? sid1 : sid2);
    StepInfo si = c_steps[sid];
    const float* W = (si.wmat == 0) ? (W0 + (size_t)DD * D2)
                                    : (Ws + (size_t)(si.wmat - 1) * DD * D2);
    bool cell = (si.pred < 0);
    const float* Asrc = cell ? hidden_in : g_states[si.pred];

    __shared__ __align__(16) float As[32 * 64];
    __shared__ float Bs[32 * 32];
    int tid = threadIdx.x;
    int p0 = blockIdx.x * 16;
    int mi = tid & 15;
    int ni = tid >> 4;
    float accC[4] = {}, accH[4] = {};

    for (int k0 = 0; k0 < DD; k0 += 32) {
        __syncthreads();
        #pragma unroll
        for (int i = 0; i < 8; i++) {          // A: 64m x 32k -> As[k][m]
            int e = tid + 256 * i;
            int m = e >> 5, k = e & 31;
            int kk = k0 + k;
            float v = 0.f;
            if (kk < DD) {
                if (!cell || t == 0) {
                    v = Asrc[m * DD + kk];
                } else {
                    float s = 0.f;
                    #pragma unroll
                    for (int j = 1; j <= 8; j++) s += g_states[j][m * DD + kk];
                    v = s * 0.125f;
                    if (blockIdx.x == 0)
                        g_hiddens[(size_t)(t - 1) * BB * DD + m * DD + kk] = v;
                }
            }
            As[k * 64 + m] = v;
        }
        #pragma unroll
        for (int i = 0; i < 4; i++) {          // W: 32k x 32col (16 c + 16 h)
            int e = tid + 256 * i;
            int k = e >> 5, col = e & 31;
            int kk = k0 + k;
            int pl = col & 15;
            int gc = (col < 16) ? (p0 + pl) : (DD + p0 + pl);
            float v = 0.f;
            if (kk < DD && (p0 + pl) < DD) v = W[(size_t)kk * D2 + gc];
            Bs[k * 32 + col] = v;
        }
        __syncthreads();
        #pragma unroll
        for (int k = 0; k < 32; k++) {
            float4 a4 = *(const float4*)(As + k * 64 + mi * 4);
            float bc = Bs[k * 32 + ni];
            float bh = Bs[k * 32 + 16 + ni];
            accC[0] = fmaf(a4.x, bc, accC[0]);
            accC[1] = fmaf(a4.y, bc, accC[1]);
            accC[2] = fmaf(a4.z, bc, accC[2]);
            accC[3] = fmaf(a4.w, bc, accC[3]);
            accH[0] = fmaf(a4.x, bh, accH[0]);
            accH[1] = fmaf(a4.y, bh, accH[1]);
            accH[2] = fmaf(a4.z, bh, accH[2]);
            accH[3] = fmaf(a4.w, bh, accH[3]);
        }
    }

    int p = p0 + ni;
    if (p < DD) {
        #pragma unroll
        for (int r = 0; r < 4; r++) {
            int m = mi * 4 + r;
            float cc = accC[r], hh = accH[r];
            float sp;
            if (cell) {
                const float* xw = g_xw0 + (size_t)t * BB * D2 + (size_t)m * D2;
                cc += xw[p];
                hh += xw[DD + p];
                if (t == 0) {
                    sp = hidden_in[m * DD + p];
                } else {
                    float s = 0.f;
                    #pragma unroll
                    for (int j = 1; j <= 8; j++) s += g_states[j][m * DD + p];
                    sp = s * 0.125f;
                }
            } else {
                sp = Asrc[m * DD + p];
            }
            float g = sigmoidf_(cc);
            float a = actf_(hh, si.act);
            g_states[sid][m * DD + p] = sp + g * (a - sp);
        }
    }
}

// ---------------------------------------------------------------------------
// K4: mean over T, decoder, log_softmax, new_hidden. One block per batch elem.
// out[0 : 64*42) = log_prob ; out[64*42 : ) = new_hidden [64*850]
// ---------------------------------------------------------------------------
__global__ void final_kernel(const float* __restrict__ masks,
                             const float* __restrict__ decW,
                             const float* __restrict__ decb,
                             float* __restrict__ out) {
    int b = blockIdx.x;
    int tid = threadIdx.x;
    __shared__ float sout[DD];
    __shared__ float lg[NCC];
    __shared__ float lse;

    float mask_last = masks[b * TT + TT - 1];
    for (int d = tid; d < DD; d += blockDim.x) {
        float ms = 0.f;
        #pragma unroll
        for (int j = 1; j <= 8; j++) ms += g_states[j][b * DD + d];
        ms *= 0.125f;
        float last_raw = ms * mask_last;
        float acc = last_raw;
        for (int t = 0; t < TT - 1; t++)
            acc += g_hiddens[(size_t)t * BB * DD + b * DD + d] * masks[b * TT + t];
        sout[d] = acc * (1.f / TT);
        out[NCC * BB + b * DD + d] = last_raw;
    }
    __syncthreads();

    for (int c = tid; c < NCC; c += blockDim.x) {
        float acc = decb[c];
        const float* w = decW + (size_t)c * DD;
        for (int d = 0; d < DD; d++) acc = fmaf(sout[d], w[d], acc);
        lg[c] = acc;
    }
    __syncthreads();

    if (tid == 0) {
        float mx = lg[0];
        for (int c = 1; c < NCC; c++) mx = fmaxf(mx, lg[c]);
        float s = 0.f;
        for (int c = 0; c < NCC; c++) s += expf(lg[c] - mx);
        lse = mx + logf(s);
    }
    __syncthreads();

    for (int c = tid; c < NCC; c += blockDim.x)
        out[b * NCC + c] = lg[c] - lse;
}

// ---------------------------------------------------------------------------
// Host launcher
// ---------------------------------------------------------------------------
extern "C" void kernel_launch(void* const* d_in, const int* in_sizes, int n_in,
                              void* d_out, int out_size) {
    const int*   tokens = (const int*)  d_in[0];
    const float* masks  = (const float*)d_in[1];
    const int*   pos    = (const int*)  d_in[2];
    const int*   ner    = (const int*)  d_in[3];
    const float* hidden = (const float*)d_in[4];
    const float* encW   = (const float*)d_in[5];
    const float* nerW   = (const float*)d_in[6];
    const float* posW   = (const float*)d_in[7];
    const float* aggW   = (const float*)d_in[8];
    const float* aggb   = (const float*)d_in[9];
    const float* W0     = (const float*)d_in[10];
    const float* Ws     = (const float*)d_in[11];
    const float* decW   = (const float*)d_in[12];
    const float* decb   = (const float*)d_in[13];
    float* out = (float*)d_out;

    float *p_combined, *p_x, *p_xw0;
    cudaGetSymbolAddress((void**)&p_combined, g_combined);
    cudaGetSymbolAddress((void**)&p_x,        g_x);
    cudaGetSymbolAddress((void**)&p_xw0,      g_xw0);

    // 1) gather embeddings
    gather_kernel<<<TT * BB, 128>>>(tokens, ner, pos, encW, nerW, posW);

    // 2) agg linear: x = combined @ aggW^T + aggb   [8192, 850]
    {
        dim3 g((DD + 63) / 64, (TT * BB) / 64);
        gemm_tile<true, true><<<g, 256>>>(p_combined, aggW, aggb, p_x,
                                          TT * BB, DD, CIN, CIN, CIN, DD);
    }
    // 3) xw0 = x @ W0[0:DD, :]   [8192, 1700]
    {
        dim3 g((D2 + 63) / 64, (TT * BB) / 64);
        gemm_tile<false, false><<<g, 256>>>(p_x, W0, nullptr, p_xw0,
                                            TT * BB, D2, DD, DD, D2, D2);
    }

    // 4) recurrence: 128 timesteps x 5 dependency levels
    const int PB = (DD + 15) / 16;   // 54 pair-blocks
    for (int t = 0; t < TT; t++) {
        recur_level<<<dim3(PB, 1), 256>>>(t, 0, 0, 0, W0, Ws, hidden);
        recur_level<<<dim3(PB, 1), 256>>>(t, 1, 1, 1, W0, Ws, hidden);
        recur_level<<<dim3(PB, 3), 256>>>(t, 2, 3, 4, W0, Ws, hidden);
        recur_level<<<dim3(PB, 2), 256>>>(t, 5, 7, 7, W0, Ws, hidden);
        recur_level<<<dim3(PB, 2), 256>>>(t, 6, 8, 8, W0, Ws, hidden);
    }

    // 5) mean over T, decoder, log_softmax, new_hidden
    final_kernel<<<BB, 256>>>(masks, decW, decb, out);
}

// round 3
// speedup vs baseline: 3.7937x; 3.7937x over previous
#include <cuda_runtime.h>
#include <math.h>
#include <stdint.h>

#define BB   64
#define TT   128
#define DD   850
#define D2   1700
#define CIN  910
#define NCC  42
#define NNER 30
#define NPOS 30
#define SD   864          // padded state stride (27*32); cols >= 850 stay zero
#define NTILE 54          // ceil(850/16) column-pair tiles

// Scratch (device globals are zero-initialized; pad columns never written)
__device__ float g_combined[TT * BB * CIN];
__device__ float g_x[TT * BB * DD];
__device__ float g_xw0[TT * BB * D2];
__device__ float g_hiddens[TT * BB * DD];
__device__ float g_state[9][BB * SD];
__device__ float g_hprev[BB * SD];
__device__ float g_part[3][2][BB * D2];
__device__ int   g_cnt[3][64];

struct StepInfo { int wmat; int pred; int act; };
// act: 0 tanh, 1 relu, 2 sigmoid, 3 identity
__constant__ StepInfo c_steps[9] = {
    {0, -1, 0},  // s0 cell (tanh)
    {1,  0, 2},  // s1 sigmoid
    {2,  1, 1},  // s2 relu
    {3,  1, 1},  // s3 relu
    {4,  1, 3},  // s4 identity
    {5,  2, 0},  // s5 tanh
    {6,  5, 2},  // s6 sigmoid
    {7,  3, 0},  // s7 tanh
    {8,  5, 1},  // s8 relu
};

__device__ __forceinline__ void cp_async16(uint32_t dst, const void* src) {
    asm volatile("cp.async.ca.shared.global [%0], [%1], 16;\n" :: "r"(dst), "l"(src));
}

// ---------------------------------------------------------------------------
// K1: gather embeddings into g_combined rows (r = t*BB + b)
// ---------------------------------------------------------------------------
__global__ void gather_kernel(const int* __restrict__ tokens,
                              const int* __restrict__ ner,
                              const int* __restrict__ pos,
                              const float* __restrict__ encW,
                              const float* __restrict__ nerW,
                              const float* __restrict__ posW) {
    int r = blockIdx.x;
    int b = r & (BB - 1);
    int t = r >> 6;
    int tok = tokens[b * TT + t];
    int nid = ner[b * TT + t];
    int pid = pos[b * TT + t];
    float* dst = g_combined + (size_t)r * CIN;
    for (int c = threadIdx.x; c < CIN; c += blockDim.x) {
        float v;
        if (c < DD)             v = encW[(size_t)tok * DD + c];
        else if (c < DD + NNER) v = nerW[nid * NNER + (c - DD)];
        else                    v = posW[pid * NPOS + (c - DD - NNER)];
        dst[c] = v;
    }
}

// ---------------------------------------------------------------------------
// K2: generic tiled fp32 GEMM, C = A * op(B) (+ bias). BM=BN=64, BK=16.
// ---------------------------------------------------------------------------
template <bool TRANSB, bool ADDBIAS>
__global__ void gemm_tile(const float* __restrict__ A, const float* __restrict__ Bm,
                          const float* __restrict__ bias, float* __restrict__ C,
                          int M, int N, int K, int lda, int ldb, int ldc) {
    __shared__ __align__(16) float As[16 * 64];
    __shared__ __align__(16) float Bs[16 * 64];
    int tid = threadIdx.x;
    int m0 = blockIdx.y * 64;
    int n0 = blockIdx.x * 64;
    int mi = tid & 15;
    int ni = tid >> 4;
    float acc[4][4] = {};

    for (int k0 = 0; k0 < K; k0 += 16) {
        __syncthreads();
        #pragma unroll
        for (int i = 0; i < 4; i++) {
            int e = tid + 256 * i;
            int m = e >> 4, k = e & 15;
            int kk = k0 + k;
            float v = 0.f;
            if (kk < K) v = A[(size_t)(m0 + m) * lda + kk];
            As[k * 64 + m] = v;
        }
        #pragma unroll
        for (int i = 0; i < 4; i++) {
            int e = tid + 256 * i;
            float v = 0.f;
            if (TRANSB) {
                int n = e >> 4, k = e & 15;
                int kk = k0 + k, nn = n0 + n;
                if (kk < K && nn < N) v = Bm[(size_t)nn * ldb + kk];
                Bs[k * 64 + n] = v;
            } else {
                int k = e >> 6, n = e & 63;
                int kk = k0 + k, nn = n0 + n;
                if (kk < K && nn < N) v = Bm[(size_t)kk * ldb + nn];
                Bs[k * 64 + n] = v;
            }
        }
        __syncthreads();
        #pragma unroll
        for (int k = 0; k < 16; k++) {
            float4 a4 = *(const float4*)(As + k * 64 + mi * 4);
            float4 b4 = *(const float4*)(Bs + k * 64 + ni * 4);
            acc[0][0] = fmaf(a4.x, b4.x, acc[0][0]);
            acc[0][1] = fmaf(a4.x, b4.y, acc[0][1]);
            acc[0][2] = fmaf(a4.x, b4.z, acc[0][2]);
            acc[0][3] = fmaf(a4.x, b4.w, acc[0][3]);
            acc[1][0] = fmaf(a4.y, b4.x, acc[1][0]);
            acc[1][1] = fmaf(a4.y, b4.y, acc[1][1]);
            acc[1][2] = fmaf(a4.y, b4.z, acc[1][2]);
            acc[1][3] = fmaf(a4.y, b4.w, acc[1][3]);
            acc[2][0] = fmaf(a4.z, b4.x, acc[2][0]);
            acc[2][1] = fmaf(a4.z, b4.y, acc[2][1]);
            acc[2][2] = fmaf(a4.z, b4.z, acc[2][2]);
            acc[2][3] = fmaf(a4.z, b4.w, acc[2][3]);
            acc[3][0] = fmaf(a4.w, b4.x, acc[3][0]);
            acc[3][1] = fmaf(a4.w, b4.y, acc[3][1]);
            acc[3][2] = fmaf(a4.w, b4.z, acc[3][2]);
            acc[3][3] = fmaf(a4.w, b4.w, acc[3][3]);
        }
    }
    #pragma unroll
    for (int r = 0; r < 4; r++) {
        int mm = m0 + mi * 4 + r;
        #pragma unroll
        for (int c = 0; c < 4; c++) {
            int nn = n0 + ni * 4 + c;
            if (nn < N) {
                float v = acc[r][c];
                if (ADDBIAS) v += bias[nn];
                C[(size_t)mm * ldc + nn] = v;
            }
        }
    }
}

// ---------------------------------------------------------------------------
// K3: prep h_prev for timestep t: t==0 copies hidden, else mean(s1..s8),
// also emitting hiddens[t-1].
// ---------------------------------------------------------------------------
__global__ void prep_hprev(int t, const float* __restrict__ hidden) {
    int i = blockIdx.x * blockDim.x + threadIdx.x;
    if (i >= BB * DD) return;
    int m = i / DD;
    int d = i - m * DD;
    float v;
    if (t == 0) {
        v = hidden[i];
    } else {
        float s = 0.f;
        #pragma unroll
        for (int j = 1; j <= 8; j++) s += g_state[j][m * SD + d];
        v = s * 0.125f;
        __stcs(&g_hiddens[(size_t)(t - 1) * BB * DD + i], v);
    }
    g_hprev[m * SD + d] = v;
}

// ---------------------------------------------------------------------------
// K4: one dependency level, split-K=2 with deterministic fixup.
// grid = (2*NTILE, nmat), block = 256. Thread = 4 m-rows x 1 col-pair.
// A double-buffered in smem via cp.async; W direct through L1.
// ---------------------------------------------------------------------------
__global__ __launch_bounds__(256, 2)
void recur2(int t, int sid0, int sid1, int sid2,
            const float* __restrict__ W0, const float* __restrict__ Ws) {
    const int mat = blockIdx.y;
    const int sid = (mat == 0) ? sid0 : (mat == 1 ? sid1 : sid2);
    const StepInfo si = c_steps[sid];
    const float* __restrict__ W = (si.wmat == 0)
        ? (W0 + (size_t)DD * D2)
        : (Ws + (size_t)(si.wmat - 1) * DD * D2);
    const float* __restrict__ A = (si.pred < 0) ? g_hprev : g_state[si.pred];

    const int tile = blockIdx.x >> 1;
    const int kh   = blockIdx.x & 1;
    const int p0 = tile * 16;
    const int tid = threadIdx.x;
    const int cp = tid & 15;
    const int mb = tid >> 4;                 // 0..15, rows mb*4..mb*4+3
    const int p = p0 + cp;
    const bool pv = (p < DD);
    const int pc = pv ? p : 0;
    const int ph = pc + DD;

    __shared__ float As[2][64][32];
    __shared__ int s_old;

    const int c0  = kh ? 14 : 0;             // chunk range: [0,14) / [14,27)
    const int nch = kh ? 13 : 14;

    const int srow = tid >> 2;
    const int sseg = (tid & 3) * 8;
    const float* gsrc = A + (size_t)srow * SD + sseg;

    float accC[4] = {0.f, 0.f, 0.f, 0.f};
    float accH[4] = {0.f, 0.f, 0.f, 0.f};

    // prologue: stage first chunk
    {
        uint32_t dst = (uint32_t)__cvta_generic_to_shared(&As[0][srow][sseg]);
        const float* src = gsrc + c0 * 32;
        cp_async16(dst, src);
        cp_async16(dst + 16, src + 4);
        asm volatile("cp.async.commit_group;\n");
    }

    for (int c = 0; c < nch; ++c) {
        const int cb = c & 1;
        if (c + 1 < nch) {
            uint32_t dst = (uint32_t)__cvta_generic_to_shared(&As[cb ^ 1][srow][sseg]);
            const float* src = gsrc + (c0 + c + 1) * 32;
            cp_async16(dst, src);
            cp_async16(dst + 16, src + 4);
            asm volatile("cp.async.commit_group;\n");
            asm volatile("cp.async.wait_group 1;\n");
        } else {
            asm volatile("cp.async.wait_group 0;\n");
        }
        __syncthreads();

        const int kg = (c0 + c) * 32;
        if (kg + 32 <= DD) {
            const float* wrow = W + (size_t)kg * D2;
            #pragma unroll
            for (int q = 0; q < 8; ++q) {
                float4 a0 = *(const float4*)&As[cb][mb * 4 + 0][q * 4];
                float4 a1 = *(const float4*)&As[cb][mb * 4 + 1][q * 4];
                float4 a2 = *(const float4*)&As[cb][mb * 4 + 2][q * 4];
                float4 a3 = *(const float4*)&As[cb][mb * 4 + 3][q * 4];
                float wc0 = wrow[pc], wh0 = wrow[ph];
                const float* w1 = wrow + D2;
                float wc1 = w1[pc], wh1 = w1[ph];
                const float* w2 = w1 + D2;
                float wc2 = w2[pc], wh2 = w2[ph];
                const float* w3 = w2 + D2;
                float wc3 = w3[pc], wh3 = w3[ph];
                wrow = w3 + D2;
                accC[0] = fmaf(a0.x, wc0, fmaf(a0.y, wc1, fmaf(a0.z, wc2, fmaf(a0.w, wc3, accC[0]))));
                accC[1] = fmaf(a1.x, wc0, fmaf(a1.y, wc1, fmaf(a1.z, wc2, fmaf(a1.w, wc3, accC[1]))));
                accC[2] = fmaf(a2.x, wc0, fmaf(a2.y, wc1, fmaf(a2.z, wc2, fmaf(a2.w, wc3, accC[2]))));
                accC[3] = fmaf(a3.x, wc0, fmaf(a3.y, wc1, fmaf(a3.z, wc2, fmaf(a3.w, wc3, accC[3]))));
                accH[0] = fmaf(a0.x, wh0, fmaf(a0.y, wh1, fmaf(a0.z, wh2, fmaf(a0.w, wh3, accH[0]))));
                accH[1] = fmaf(a1.x, wh0, fmaf(a1.y, wh1, fmaf(a1.z, wh2, fmaf(a1.w, wh3, accH[1]))));
                accH[2] = fmaf(a2.x, wh0, fmaf(a2.y, wh1, fmaf(a2.z, wh2, fmaf(a2.w, wh3, accH[2]))));
                accH[3] = fmaf(a3.x, wh0, fmaf(a3.y, wh1, fmaf(a3.z, wh2, fmaf(a3.w, wh3, accH[3]))));
            }
        } else {
            // tail chunk: A pad columns are zero, clamp W row index to stay in bounds
            #pragma unroll 4
            for (int kk = 0; kk < 32; ++kk) {
                int k = kg + kk;
                int wk = (k < DD) ? k : (DD - 1);
                float wc = W[(size_t)wk * D2 + pc];
                float wh = W[(size_t)wk * D2 + ph];
                #pragma unroll
                for (int r = 0; r < 4; ++r) {
                    float a = As[cb][mb * 4 + r][kk];
                    accC[r] = fmaf(a, wc, accC[r]);
                    accH[r] = fmaf(a, wh, accH[r]);
                }
            }
        }
        __syncthreads();
    }

    // ---- split-K fixup: write partials, last CTA of the pair does epilogue ----
    float* pt = g_part[mat][kh];
    if (pv) {
        #pragma unroll
        for (int r = 0; r < 4; ++r) {
            int m = mb * 4 + r;
            pt[(size_t)m * D2 + p]      = accC[r];
            pt[(size_t)m * D2 + DD + p] = accH[r];
        }
    }
    __threadfence();
    __syncthreads();
    if (tid == 0) s_old = atomicAdd(&g_cnt[mat][tile], 1);
    __syncthreads();
    if (s_old == 1) {
        __threadfence();
        const float* po = g_part[mat][kh ^ 1];
        if (pv) {
            #pragma unroll
            for (int r = 0; r < 4; ++r) {
                int m = mb * 4 + r;
                float cc = accC[r] + po[(size_t)m * D2 + p];
                float hh = accH[r] + po[(size_t)m * D2 + DD + p];
                if (si.pred < 0) {
                    const float* xw = g_xw0 + ((size_t)t * BB + m) * D2;
                    cc += __ldcs(xw + p);
                    hh += __ldcs(xw + DD + p);
                }
                float sp = A[(size_t)m * SD + p];
                float g = 1.f / (1.f + expf(-cc));
                float av = (si.act == 0) ? tanhf(hh)
                         : (si.act == 1) ? fmaxf(hh, 0.f)
                         : (si.act == 2) ? 1.f / (1.f + expf(-hh)) : hh;
                g_state[sid][(size_t)m * SD + p] = sp + g * (av - sp);
            }
        }
        __syncthreads();
        if (tid == 0) g_cnt[mat][tile] = 0;
    }
}

// ---------------------------------------------------------------------------
// K5: mean over T, decoder, log_softmax, new_hidden. One block per batch elem.
// out[0 : 64*42) = log_prob ; out[64*42 : ) = new_hidden [64*850]
// ---------------------------------------------------------------------------
__global__ void final_kernel(const float* __restrict__ masks,
                             const float* __restrict__ decW,
                             const float* __restrict__ decb,
                             float* __restrict__ out) {
    int b = blockIdx.x;
    int tid = threadIdx.x;
    __shared__ float sout[DD];
    __shared__ float lg[NCC];
    __shared__ float lse;

    float mask_last = masks[b * TT + TT - 1];
    for (int d = tid; d < DD; d += blockDim.x) {
        float ms = 0.f;
        #pragma unroll
        for (int j = 1; j <= 8; j++) ms += g_state[j][b * SD + d];
        ms *= 0.125f;
        float last_raw = ms * mask_last;
        float acc = last_raw;
        for (int t = 0; t < TT - 1; t++)
            acc += g_hiddens[(size_t)t * BB * DD + b * DD + d] * masks[b * TT + t];
        sout[d] = acc * (1.f / TT);
        out[NCC * BB + b * DD + d] = last_raw;
    }
    __syncthreads();

    for (int c = tid; c < NCC; c += blockDim.x) {
        float acc = decb[c];
        const float* w = decW + (size_t)c * DD;
        for (int d = 0; d < DD; d++) acc = fmaf(sout[d], w[d], acc);
        lg[c] = acc;
    }
    __syncthreads();

    if (tid == 0) {
        float mx = lg[0];
        for (int c = 1; c < NCC; c++) mx = fmaxf(mx, lg[c]);
        float s = 0.f;
        for (int c = 0; c < NCC; c++) s += expf(lg[c] - mx);
        lse = mx + logf(s);
    }
    __syncthreads();

    for (int c = tid; c < NCC; c += blockDim.x)
        out[b * NCC + c] = lg[c] - lse;
}

// ---------------------------------------------------------------------------
// Host launcher
// ---------------------------------------------------------------------------
extern "C" void kernel_launch(void* const* d_in, const int* in_sizes, int n_in,
                              void* d_out, int out_size) {
    const int*   tokens = (const int*)  d_in[0];
    const float* masks  = (const float*)d_in[1];
    const int*   pos    = (const int*)  d_in[2];
    const int*   ner    = (const int*)  d_in[3];
    const float* hidden = (const float*)d_in[4];
    const float* encW   = (const float*)d_in[5];
    const float* nerW   = (const float*)d_in[6];
    const float* posW   = (const float*)d_in[7];
    const float* aggW   = (const float*)d_in[8];
    const float* aggb   = (const float*)d_in[9];
    const float* W0     = (const float*)d_in[10];
    const float* Ws     = (const float*)d_in[11];
    const float* decW   = (const float*)d_in[12];
    const float* decb   = (const float*)d_in[13];
    float* out = (float*)d_out;

    float *p_combined, *p_x, *p_xw0;
    cudaGetSymbolAddress((void**)&p_combined, g_combined);
    cudaGetSymbolAddress((void**)&p_x,        g_x);
    cudaGetSymbolAddress((void**)&p_xw0,      g_xw0);

    // 1) gather embeddings
    gather_kernel<<<TT * BB, 128>>>(tokens, ner, pos, encW, nerW, posW);

    // 2) agg linear: x = combined @ aggW^T + aggb   [8192, 850]
    {
        dim3 g((DD + 63) / 64, (TT * BB) / 64);
        gemm_tile<true, true><<<g, 256>>>(p_combined, aggW, aggb, p_x,
                                          TT * BB, DD, CIN, CIN, CIN, DD);
    }
    // 3) xw0 = x @ W0[0:DD, :]   [8192, 1700]
    {
        dim3 g((D2 + 63) / 64, (TT * BB) / 64);
        gemm_tile<false, false><<<g, 256>>>(p_x, W0, nullptr, p_xw0,
                                            TT * BB, D2, DD, DD, D2, D2);
    }

    // 4) recurrence: 128 timesteps x (prep + 5 levels), split-K=2 everywhere
    const int PREP_G = (BB * DD + 255) / 256;
    for (int t = 0; t < TT; t++) {
        prep_hprev<<<PREP_G, 256>>>(t, hidden);
        recur2<<<dim3(2 * NTILE, 1), 256>>>(t, 0, 0, 0, W0, Ws);
        recur2<<<dim3(2 * NTILE, 1), 256>>>(t, 1, 1, 1, W0, Ws);
        recur2<<<dim3(2 * NTILE, 3), 256>>>(t, 2, 3, 4, W0, Ws);
        recur2<<<dim3(2 * NTILE, 2), 256>>>(t, 5, 7, 7, W0, Ws);
        recur2<<<dim3(2 * NTILE, 2), 256>>>(t, 6, 8, 8, W0, Ws);
    }

    // 5) mean over T, decoder, log_softmax, new_hidden
    final_kernel<<<BB, 256>>>(masks, decW, decb, out);
}

// round 4
// speedup vs baseline: 3.8048x; 1.0029x over previous
#include <cuda_runtime.h>
#include <math.h>
#include <stdint.h>

#define BB   64
#define TT   128
#define DD   850
#define D2   1700
#define CIN  910
#define NCC  42
#define NNER 30
#define NPOS 30
#define SD   864          // padded state stride (27*32); cols >= 850 stay zero
#define NTILE 54          // ceil(850/16) column-pair tiles

// Scratch (device globals are zero-initialized; pad columns never written)
__device__ float g_combined[TT * BB * CIN];
__device__ float g_x[TT * BB * DD];
__device__ float g_xw0[TT * BB * D2];
__device__ float g_hiddens[TT * BB * DD];
__device__ float g_state[9][BB * SD];
__device__ float g_hprev[BB * SD];
__device__ float g_part[3][2][BB * D2];
__device__ int   g_cnt[3][64];

struct StepInfo { int wmat; int pred; int act; };
// act: 0 tanh, 1 relu, 2 sigmoid, 3 identity
__constant__ StepInfo c_steps[9] = {
    {0, -1, 0},  // s0 cell (tanh)
    {1,  0, 2},  // s1 sigmoid
    {2,  1, 1},  // s2 relu
    {3,  1, 1},  // s3 relu
    {4,  1, 3},  // s4 identity
    {5,  2, 0},  // s5 tanh
    {6,  5, 2},  // s6 sigmoid
    {7,  3, 0},  // s7 tanh
    {8,  5, 1},  // s8 relu
};

__device__ __forceinline__ void cp_async16(uint32_t dst, const void* src) {
    asm volatile("cp.async.ca.shared.global [%0], [%1], 16;\n" :: "r"(dst), "l"(src));
}

// ---------------------------------------------------------------------------
// K1: gather embeddings into g_combined rows (r = t*BB + b)
// ---------------------------------------------------------------------------
__global__ void gather_kernel(const int* __restrict__ tokens,
                              const int* __restrict__ ner,
                              const int* __restrict__ pos,
                              const float* __restrict__ encW,
                              const float* __restrict__ nerW,
                              const float* __restrict__ posW) {
    int r = blockIdx.x;
    int b = r & (BB - 1);
    int t = r >> 6;
    int tok = tokens[b * TT + t];
    int nid = ner[b * TT + t];
    int pid = pos[b * TT + t];
    float* dst = g_combined + (size_t)r * CIN;
    for (int c = threadIdx.x; c < CIN; c += blockDim.x) {
        float v;
        if (c < DD)             v = encW[(size_t)tok * DD + c];
        else if (c < DD + NNER) v = nerW[nid * NNER + (c - DD)];
        else                    v = posW[pid * NPOS + (c - DD - NNER)];
        dst[c] = v;
    }
}

// ---------------------------------------------------------------------------
// K2: generic tiled fp32 GEMM, C = A * op(B) (+ bias). BM=BN=64, BK=16.
// ---------------------------------------------------------------------------
template <bool TRANSB, bool ADDBIAS>
__global__ void gemm_tile(const float* __restrict__ A, const float* __restrict__ Bm,
                          const float* __restrict__ bias, float* __restrict__ C,
                          int M, int N, int K, int lda, int ldb, int ldc) {
    __shared__ __align__(16) float As[16 * 64];
    __shared__ __align__(16) float Bs[16 * 64];
    int tid = threadIdx.x;
    int m0 = blockIdx.y * 64;
    int n0 = blockIdx.x * 64;
    int mi = tid & 15;
    int ni = tid >> 4;
    float acc[4][4] = {};

    for (int k0 = 0; k0 < K; k0 += 16) {
        __syncthreads();
        #pragma unroll
        for (int i = 0; i < 4; i++) {
            int e = tid + 256 * i;
            int m = e >> 4, k = e & 15;
            int kk = k0 + k;
            float v = 0.f;
            if (kk < K) v = A[(size_t)(m0 + m) * lda + kk];
            As[k * 64 + m] = v;
        }
        #pragma unroll
        for (int i = 0; i < 4; i++) {
            int e = tid + 256 * i;
            float v = 0.f;
            if (TRANSB) {
                int n = e >> 4, k = e & 15;
                int kk = k0 + k, nn = n0 + n;
                if (kk < K && nn < N) v = Bm[(size_t)nn * ldb + kk];
                Bs[k * 64 + n] = v;
            } else {
                int k = e >> 6, n = e & 63;
                int kk = k0 + k, nn = n0 + n;
                if (kk < K && nn < N) v = Bm[(size_t)kk * ldb + nn];
                Bs[k * 64 + n] = v;
            }
        }
        __syncthreads();
        #pragma unroll
        for (int k = 0; k < 16; k++) {
            float4 a4 = *(const float4*)(As + k * 64 + mi * 4);
            float4 b4 = *(const float4*)(Bs + k * 64 + ni * 4);
            acc[0][0] = fmaf(a4.x, b4.x, acc[0][0]);
            acc[0][1] = fmaf(a4.x, b4.y, acc[0][1]);
            acc[0][2] = fmaf(a4.x, b4.z, acc[0][2]);
            acc[0][3] = fmaf(a4.x, b4.w, acc[0][3]);
            acc[1][0] = fmaf(a4.y, b4.x, acc[1][0]);
            acc[1][1] = fmaf(a4.y, b4.y, acc[1][1]);
            acc[1][2] = fmaf(a4.y, b4.z, acc[1][2]);
            acc[1][3] = fmaf(a4.y, b4.w, acc[1][3]);
            acc[2][0] = fmaf(a4.z, b4.x, acc[2][0]);
            acc[2][1] = fmaf(a4.z, b4.y, acc[2][1]);
            acc[2][2] = fmaf(a4.z, b4.z, acc[2][2]);
            acc[2][3] = fmaf(a4.z, b4.w, acc[2][3]);
            acc[3][0] = fmaf(a4.w, b4.x, acc[3][0]);
            acc[3][1] = fmaf(a4.w, b4.y, acc[3][1]);
            acc[3][2] = fmaf(a4.w, b4.z, acc[3][2]);
            acc[3][3] = fmaf(a4.w, b4.w, acc[3][3]);
        }
    }
    #pragma unroll
    for (int r = 0; r < 4; r++) {
        int mm = m0 + mi * 4 + r;
        #pragma unroll
        for (int c = 0; c < 4; c++) {
            int nn = n0 + ni * 4 + c;
            if (nn < N) {
                float v = acc[r][c];
                if (ADDBIAS) v += bias[nn];
                C[(size_t)mm * ldc + nn] = v;
            }
        }
    }
}

// ---------------------------------------------------------------------------
// K3: prep h_prev for timestep t: t==0 copies hidden, else mean(s1..s8),
// also emitting hiddens[t-1].
// ---------------------------------------------------------------------------
__global__ void prep_hprev(int t, const float* __restrict__ hidden) {
    int i = blockIdx.x * blockDim.x + threadIdx.x;
    if (i >= BB * DD) return;
    int m = i / DD;
    int d = i - m * DD;
    float v;
    if (t == 0) {
        v = hidden[i];
    } else {
        float s = 0.f;
        #pragma unroll
        for (int j = 1; j <= 8; j++) s += g_state[j][m * SD + d];
        v = s * 0.125f;
        __stcs(&g_hiddens[(size_t)(t - 1) * BB * DD + i], v);
    }
    g_hprev[m * SD + d] = v;
}

// ---------------------------------------------------------------------------
// K4: one dependency level, split-K=2 with deterministic fixup.
// grid = (2*NTILE, nmat), block = 256. Thread = 4 m-rows x 1 col-pair.
// A double-buffered in smem via cp.async; W direct through L1.
// ---------------------------------------------------------------------------
__global__ __launch_bounds__(256, 2)
void recur2(int t, int sid0, int sid1, int sid2,
            const float* __restrict__ W0, const float* __restrict__ Ws) {
    const int mat = blockIdx.y;
    const int sid = (mat == 0) ? sid0 : (mat == 1 ? sid1 : sid2);
    const StepInfo si = c_steps[sid];
    const float* __restrict__ W = (si.wmat == 0)
        ? (W0 + (size_t)DD * D2)
        : (Ws + (size_t)(si.wmat - 1) * DD * D2);
    const float* __restrict__ A = (si.pred < 0) ? g_hprev : g_state[si.pred];

    const int tile = blockIdx.x >> 1;
    const int kh   = blockIdx.x & 1;
    const int p0 = tile * 16;
    const int tid = threadIdx.x;
    const int cp = tid & 15;
    const int mb = tid >> 4;                 // 0..15, rows mb*4..mb*4+3
    const int p = p0 + cp;
    const bool pv = (p < DD);
    const int pc = pv ? p : 0;
    const int ph = pc + DD;

    __shared__ float As[2][64][32];
    __shared__ int s_old;

    const int c0  = kh ? 14 : 0;             // chunk range: [0,14) / [14,27)
    const int nch = kh ? 13 : 14;

    const int srow = tid >> 2;
    const int sseg = (tid & 3) * 8;
    const float* gsrc = A + (size_t)srow * SD + sseg;

    float accC[4] = {0.f, 0.f, 0.f, 0.f};
    float accH[4] = {0.f, 0.f, 0.f, 0.f};

    // prologue: stage first chunk
    {
        uint32_t dst = (uint32_t)__cvta_generic_to_shared(&As[0][srow][sseg]);
        const float* src = gsrc + c0 * 32;
        cp_async16(dst, src);
        cp_async16(dst + 16, src + 4);
        asm volatile("cp.async.commit_group;\n");
    }

    for (int c = 0; c < nch; ++c) {
        const int cb = c & 1;
        if (c + 1 < nch) {
            uint32_t dst = (uint32_t)__cvta_generic_to_shared(&As[cb ^ 1][srow][sseg]);
            const float* src = gsrc + (c0 + c + 1) * 32;
            cp_async16(dst, src);
            cp_async16(dst + 16, src + 4);
            asm volatile("cp.async.commit_group;\n");
            asm volatile("cp.async.wait_group 1;\n");
        } else {
            asm volatile("cp.async.wait_group 0;\n");
        }
        __syncthreads();

        const int kg = (c0 + c) * 32;
        if (kg + 32 <= DD) {
            const float* wrow = W + (size_t)kg * D2;
            #pragma unroll
            for (int q = 0; q < 8; ++q) {
                float4 a0 = *(const float4*)&As[cb][mb * 4 + 0][q * 4];
                float4 a1 = *(const float4*)&As[cb][mb * 4 + 1][q * 4];
                float4 a2 = *(const float4*)&As[cb][mb * 4 + 2][q * 4];
                float4 a3 = *(const float4*)&As[cb][mb * 4 + 3][q * 4];
                float wc0 = wrow[pc], wh0 = wrow[ph];
                const float* w1 = wrow + D2;
                float wc1 = w1[pc], wh1 = w1[ph];
                const float* w2 = w1 + D2;
                float wc2 = w2[pc], wh2 = w2[ph];
                const float* w3 = w2 + D2;
                float wc3 = w3[pc], wh3 = w3[ph];
                wrow = w3 + D2;
                accC[0] = fmaf(a0.x, wc0, fmaf(a0.y, wc1, fmaf(a0.z, wc2, fmaf(a0.w, wc3, accC[0]))));
                accC[1] = fmaf(a1.x, wc0, fmaf(a1.y, wc1, fmaf(a1.z, wc2, fmaf(a1.w, wc3, accC[1]))));
                accC[2] = fmaf(a2.x, wc0, fmaf(a2.y, wc1, fmaf(a2.z, wc2, fmaf(a2.w, wc3, accC[2]))));
                accC[3] = fmaf(a3.x, wc0, fmaf(a3.y, wc1, fmaf(a3.z, wc2, fmaf(a3.w, wc3, accC[3]))));
                accH[0] = fmaf(a0.x, wh0, fmaf(a0.y, wh1, fmaf(a0.z, wh2, fmaf(a0.w, wh3, accH[0]))));
                accH[1] = fmaf(a1.x, wh0, fmaf(a1.y, wh1, fmaf(a1.z, wh2, fmaf(a1.w, wh3, accH[1]))));
                accH[2] = fmaf(a2.x, wh0, fmaf(a2.y, wh1, fmaf(a2.z, wh2, fmaf(a2.w, wh3, accH[2]))));
                accH[3] = fmaf(a3.x, wh0, fmaf(a3.y, wh1, fmaf(a3.z, wh2, fmaf(a3.w, wh3, accH[3]))));
            }
        } else {
            // tail chunk: A pad columns are zero, clamp W row index to stay in bounds
            #pragma unroll 4
            for (int kk = 0; kk < 32; ++kk) {
                int k = kg + kk;
                int wk = (k < DD) ? k : (DD - 1);
                float wc = W[(size_t)wk * D2 + pc];
                float wh = W[(size_t)wk * D2 + ph];
                #pragma unroll
                for (int r = 0; r < 4; ++r) {
                    float a = As[cb][mb * 4 + r][kk];
                    accC[r] = fmaf(a, wc, accC[r]);
                    accH[r] = fmaf(a, wh, accH[r]);
                }
            }
        }
        __syncthreads();
    }

    // ---- split-K fixup: write partials, last CTA of the pair does epilogue ----
    float* pt = g_part[mat][kh];
    if (pv) {
        #pragma unroll
        for (int r = 0; r < 4; ++r) {
            int m = mb * 4 + r;
            pt[(size_t)m * D2 + p]      = accC[r];
            pt[(size_t)m * D2 + DD + p] = accH[r];
        }
    }
    __threadfence();
    __syncthreads();
    if (tid == 0) s_old = atomicAdd(&g_cnt[mat][tile], 1);
    __syncthreads();
    if (s_old == 1) {
        __threadfence();
        const float* po = g_part[mat][kh ^ 1];
        if (pv) {
            #pragma unroll
            for (int r = 0; r < 4; ++r) {
                int m = mb * 4 + r;
                float cc = accC[r] + po[(size_t)m * D2 + p];
                float hh = accH[r] + po[(size_t)m * D2 + DD + p];
                if (si.pred < 0) {
                    const float* xw = g_xw0 + ((size_t)t * BB + m) * D2;
                    cc += __ldcs(xw + p);
                    hh += __ldcs(xw + DD + p);
                }
                float sp = A[(size_t)m * SD + p];
                float g = 1.f / (1.f + expf(-cc));
                float av = (si.act == 0) ? tanhf(hh)
                         : (si.act == 1) ? fmaxf(hh, 0.f)
                         : (si.act == 2) ? 1.f / (1.f + expf(-hh)) : hh;
                g_state[sid][(size_t)m * SD + p] = sp + g * (av - sp);
            }
        }
        __syncthreads();
        if (tid == 0) g_cnt[mat][tile] = 0;
    }
}

// ---------------------------------------------------------------------------
// K5: mean over T, decoder, log_softmax, new_hidden. One block per batch elem.
// out[0 : 64*42) = log_prob ; out[64*42 : ) = new_hidden [64*850]
// ---------------------------------------------------------------------------
__global__ void final_kernel(const float* __restrict__ masks,
                             const float* __restrict__ decW,
                             const float* __restrict__ decb,
                             float* __restrict__ out) {
    int b = blockIdx.x;
    int tid = threadIdx.x;
    __shared__ float sout[DD];
    __shared__ float lg[NCC];
    __shared__ float lse;

    float mask_last = masks[b * TT + TT - 1];
    for (int d = tid; d < DD; d += blockDim.x) {
        float ms = 0.f;
        #pragma unroll
        for (int j = 1; j <= 8; j++) ms += g_state[j][b * SD + d];
        ms *= 0.125f;
        float last_raw = ms * mask_last;
        float acc = last_raw;
        for (int t = 0; t < TT - 1; t++)
            acc += g_hiddens[(size_t)t * BB * DD + b * DD + d] * masks[b * TT + t];
        sout[d] = acc * (1.f / TT);
        out[NCC * BB + b * DD + d] = last_raw;
    }
    __syncthreads();

    for (int c = tid; c < NCC; c += blockDim.x) {
        float acc = decb[c];
        const float* w = decW + (size_t)c * DD;
        for (int d = 0; d < DD; d++) acc = fmaf(sout[d], w[d], acc);
        lg[c] = acc;
    }
    __syncthreads();

    if (tid == 0) {
        float mx = lg[0];
        for (int c = 1; c < NCC; c++) mx = fmaxf(mx, lg[c]);
        float s = 0.f;
        for (int c = 0; c < NCC; c++) s += expf(lg[c] - mx);
        lse = mx + logf(s);
    }
    __syncthreads();

    for (int c = tid; c < NCC; c += blockDim.x)
        out[b * NCC + c] = lg[c] - lse;
}

// ---------------------------------------------------------------------------
// Host launcher
// ---------------------------------------------------------------------------
extern "C" void kernel_launch(void* const* d_in, const int* in_sizes, int n_in,
                              void* d_out, int out_size) {
    const int*   tokens = (const int*)  d_in[0];
    const float* masks  = (const float*)d_in[1];
    const int*   pos    = (const int*)  d_in[2];
    const int*   ner    = (const int*)  d_in[3];
    const float* hidden = (const float*)d_in[4];
    const float* encW   = (const float*)d_in[5];
    const float* nerW   = (const float*)d_in[6];
    const float* posW   = (const float*)d_in[7];
    const float* aggW   = (const float*)d_in[8];
    const float* aggb   = (const float*)d_in[9];
    const float* W0     = (const float*)d_in[10];
    const float* Ws     = (const float*)d_in[11];
    const float* decW   = (const float*)d_in[12];
    const float* decb   = (const float*)d_in[13];
    float* out = (float*)d_out;

    float *p_combined, *p_x, *p_xw0;
    cudaGetSymbolAddress((void**)&p_combined, g_combined);
    cudaGetSymbolAddress((void**)&p_x,        g_x);
    cudaGetSymbolAddress((void**)&p_xw0,      g_xw0);

    // 1) gather embeddings
    gather_kernel<<<TT * BB, 128>>>(tokens, ner, pos, encW, nerW, posW);

    // 2) agg linear: x = combined @ aggW^T + aggb   [8192, 850]
    {
        dim3 g((DD + 63) / 64, (TT * BB) / 64);
        gemm_tile<true, true><<<g, 256>>>(p_combined, aggW, aggb, p_x,
                                          TT * BB, DD, CIN, CIN, CIN, DD);
    }
    // 3) xw0 = x @ W0[0:DD, :]   [8192, 1700]
    {
        dim3 g((D2 + 63) / 64, (TT * BB) / 64);
        gemm_tile<false, false><<<g, 256>>>(p_x, W0, nullptr, p_xw0,
                                            TT * BB, D2, DD, DD, D2, D2);
    }

    // 4) recurrence: 128 timesteps x (prep + 5 levels), split-K=2 everywhere
    const int PREP_G = (BB * DD + 255) / 256;
    for (int t = 0; t < TT; t++) {
        prep_hprev<<<PREP_G, 256>>>(t, hidden);
        recur2<<<dim3(2 * NTILE, 1), 256>>>(t, 0, 0, 0, W0, Ws);
        recur2<<<dim3(2 * NTILE, 1), 256>>>(t, 1, 1, 1, W0, Ws);
        recur2<<<dim3(2 * NTILE, 3), 256>>>(t, 2, 3, 4, W0, Ws);
        recur2<<<dim3(2 * NTILE, 2), 256>>>(t, 5, 7, 7, W0, Ws);
        recur2<<<dim3(2 * NTILE, 2), 256>>>(t, 6, 8, 8, W0, Ws);
    }

    // 5) mean over T, decoder, log_softmax, new_hidden
    final_kernel<<<BB, 256>>>(masks, decW, decb, out);
}